// round 8
// baseline (speedup 1.0000x reference)
#include <cuda_runtime.h>
#include <cuda_fp16.h>
#include <math.h>
#include <stdint.h>

#define EMBED  512
#define NHEADS 8
#define HDIM   64
#define BATCH  4
#define SEQ    2048
#define MTOT   (BATCH*SEQ)   // 8192

// Scratch (device globals — no runtime allocation)
__device__ __half g_xh[MTOT*EMBED];             // x in fp16
__device__ __half g_wh[4*EMBED*EMBED];          // Wq,Wk,Wv,Wo in fp16
__device__ __half g_q[BATCH*NHEADS*SEQ*HDIM];   // [B,H,S,D] fp16
__device__ __half g_k[BATCH*NHEADS*SEQ*HDIM];   // [B,H,S,D] fp16
__device__ __half g_v[BATCH*NHEADS*SEQ*HDIM];   // [B,H,S,D] fp16
__device__ __half g_o[BATCH*SEQ*EMBED];         // [B,S,E] fp16

__device__ __forceinline__ float gelu_f(float x) {
    return 0.5f * x * (1.0f + erff(x * 0.70710678118654752440f));
}

__device__ __forceinline__ uint32_t packh(float a, float b) {
    __half2 h = __floats2half2_rn(a, b);
    return *(uint32_t*)&h;
}

__device__ __forceinline__ float fexp2(float x) {
    float y;
    asm("ex2.approx.ftz.f32 %0, %1;" : "=f"(y) : "f"(x));
    return y;
}

__device__ __forceinline__ uint32_t sptr(const void* p) {
    return (uint32_t)__cvta_generic_to_shared(p);
}

__device__ __forceinline__ void cpasync16(uint32_t dst, const void* src) {
    asm volatile("cp.async.ca.shared.global [%0], [%1], 16;" :: "r"(dst), "l"(src));
}
__device__ __forceinline__ void cp_commit() {
    asm volatile("cp.async.commit_group;");
}
template<int N>
__device__ __forceinline__ void cp_wait() {
    asm volatile("cp.async.wait_group %0;" :: "n"(N));
}

__device__ __forceinline__ void mma_f16(float c[4], const uint32_t a[4], const uint32_t b[2]) {
    asm volatile(
        "mma.sync.aligned.m16n8k16.row.col.f32.f16.f16.f32 "
        "{%0,%1,%2,%3},{%4,%5,%6,%7},{%8,%9},{%0,%1,%2,%3};"
        : "+f"(c[0]), "+f"(c[1]), "+f"(c[2]), "+f"(c[3])
        : "r"(a[0]), "r"(a[1]), "r"(a[2]), "r"(a[3]), "r"(b[0]), "r"(b[1]));
}

__device__ __forceinline__ void ldsm4(uint32_t r[4], uint32_t saddr) {
    asm volatile("ldmatrix.sync.aligned.m8n8.x4.shared.b16 {%0,%1,%2,%3}, [%4];"
                 : "=r"(r[0]), "=r"(r[1]), "=r"(r[2]), "=r"(r[3]) : "r"(saddr));
}

__device__ __forceinline__ void ldsm4t(uint32_t r[4], uint32_t saddr) {
    asm volatile("ldmatrix.sync.aligned.m8n8.x4.trans.shared.b16 {%0,%1,%2,%3}, [%4];"
                 : "=r"(r[0]), "=r"(r[1]), "=r"(r[2]), "=r"(r[3]) : "r"(saddr));
}

// ---------------------------------------------------------------------------
// Convert x and all four weight matrices to fp16 (one memory-bound pass).
// ---------------------------------------------------------------------------
__global__ __launch_bounds__(256)
void convert_f2h(const float* __restrict__ x,
                 const float* __restrict__ Wq, const float* __restrict__ Wk,
                 const float* __restrict__ Wv, const float* __restrict__ Wo) {
    const int XC = MTOT * EMBED / 4;    // float4 chunks of x
    const int WC = EMBED * EMBED / 4;   // float4 chunks per W
    int i = blockIdx.x * 256 + threadIdx.x;
    float4 v;
    uint2* dst;
    if (i < XC) {
        v = ((const float4*)x)[i];
        dst = (uint2*)g_xh + i;
    } else {
        int j = i - XC;
        int w = j / WC, off = j - w * WC;
        const float* Ws = (w == 0) ? Wq : (w == 1) ? Wk : (w == 2) ? Wv : Wo;
        v = ((const float4*)Ws)[off];
        dst = (uint2*)g_wh + j;
    }
    uint2 p;
    p.x = packh(v.x, v.y);
    p.y = packh(v.z, v.w);
    *dst = p;
}

// ---------------------------------------------------------------------------
// GEMM core: C = gelu(A @ W^T + bias). A,W fp16. Block tile 128x128, 8 warps
// (2m x 4n), warp tile 64x32, BK=32, cp.async double-buffered.
// OHALF: out fp16 [B,H,S,D]; else fp32 flat [M,512].
// ---------------------------------------------------------------------------
template<bool OHALF>
__device__ __forceinline__ void gemm_core(const __half* __restrict__ A,
                                          const __half* __restrict__ W,
                                          const float* __restrict__ bias, void* Cout) {
    __shared__ uint32_t As[2][128][20];
    __shared__ uint32_t Ws[2][128][20];

    const int t    = threadIdx.x;
    const int lane = t & 31;
    const int warp = t >> 5;
    const int wm   = warp >> 2;       // 0..1
    const int wn   = warp & 3;        // 0..3
    const int m0   = blockIdx.y * 128;
    const int n0   = blockIdx.x * 128;
    const int r    = lane >> 2;
    const int cc   = lane & 3;

    const int lrow = t >> 1;          // 0..127
    const int lw   = (t & 1) * 8;     // word offset {0, 8} (16 halves per thread)

    const uint32_t a_loff = (((lane & 15) * 20) + ((lane >> 4) * 4)) * 4;
    const uint32_t b_loff = ((((lane & 7) + ((lane >> 4) * 8)) * 20) + (((lane >> 3) & 1) * 4)) * 4;
    const uint32_t as_w = sptr(&As[0][0][0]) + (uint32_t)(wm * 64 * 20) * 4 + a_loff;
    const uint32_t ws_w = sptr(&Ws[0][0][0]) + (uint32_t)(wn * 32 * 20) * 4 + b_loff;
    const uint32_t BUFB = 128 * 20 * 4;  // buffer stride in bytes

    const __half* abase = A + (size_t)(m0 + lrow) * EMBED + lw * 2;
    const __half* wbase = W + (size_t)(n0 + lrow) * EMBED + lw * 2;
    const uint32_t adst = sptr(&As[0][lrow][lw]);
    const uint32_t wdst = sptr(&Ws[0][lrow][lw]);

    float acc[4][4][4];
    #pragma unroll
    for (int mi = 0; mi < 4; ++mi)
        #pragma unroll
        for (int ni = 0; ni < 4; ++ni)
            #pragma unroll
            for (int j = 0; j < 4; ++j) acc[mi][ni][j] = 0.0f;

    // prologue: issue tile 0
    cpasync16(adst, abase);
    cpasync16(adst + 16, abase + 8);
    cpasync16(wdst, wbase);
    cpasync16(wdst + 16, wbase + 8);
    cp_commit();

    #pragma unroll 1
    for (int i = 0; i < 16; ++i) {
        const int buf = i & 1;
        if (i < 15) {
            const int k0 = (i + 1) * 32;
            const uint32_t boff = (buf ^ 1) * BUFB;
            cpasync16(adst + boff, abase + k0);
            cpasync16(adst + boff + 16, abase + k0 + 8);
            cpasync16(wdst + boff, wbase + k0);
            cpasync16(wdst + boff + 16, wbase + k0 + 8);
            cp_commit();
            cp_wait<1>();
        } else {
            cp_wait<0>();
        }
        __syncthreads();

        const uint32_t aw = as_w + buf * BUFB;
        const uint32_t ww = ws_w + buf * BUFB;
        #pragma unroll
        for (int ks = 0; ks < 2; ++ks) {
            uint32_t a[4][4], b[2][4];
            #pragma unroll
            for (int mi = 0; mi < 4; ++mi)
                ldsm4(a[mi], aw + (uint32_t)(mi * 16 * 20) * 4 + ks * 32);
            #pragma unroll
            for (int np = 0; np < 2; ++np)
                ldsm4(b[np], ww + (uint32_t)(np * 16 * 20) * 4 + ks * 32);
            #pragma unroll
            for (int mi = 0; mi < 4; ++mi)
                #pragma unroll
                for (int np = 0; np < 2; ++np) {
                    mma_f16(acc[mi][2 * np],     a[mi], &b[np][0]);
                    mma_f16(acc[mi][2 * np + 1], a[mi], &b[np][2]);
                }
        }
        __syncthreads();
    }

    // Epilogue: bias + gelu, store
    #pragma unroll
    for (int mi = 0; mi < 4; ++mi) {
        #pragma unroll
        for (int ni = 0; ni < 4; ++ni) {
            int row = m0 + wm * 64 + mi * 16 + r;
            int col = n0 + wn * 32 + ni * 8 + 2 * cc;
            float b0 = bias[col], b1 = bias[col + 1];
            float e00 = gelu_f(acc[mi][ni][0] + b0);
            float e01 = gelu_f(acc[mi][ni][1] + b1);
            float e10 = gelu_f(acc[mi][ni][2] + b0);
            float e11 = gelu_f(acc[mi][ni][3] + b1);
            if (!OHALF) {
                float* C = (float*)Cout;
                float2 v0 = {e00, e01}, v1 = {e10, e11};
                *(float2*)(C + (size_t)row * EMBED + col)       = v0;
                *(float2*)(C + (size_t)(row + 8) * EMBED + col) = v1;
            } else {
                __half* C = (__half*)Cout;
                int bz = row >> 11, s = row & (SEQ - 1);
                int h = col >> 6, d = col & 63;
                *(uint32_t*)&C[(((size_t)(bz * NHEADS + h) * SEQ + s) * HDIM + d)]       = packh(e00, e01);
                *(uint32_t*)&C[(((size_t)(bz * NHEADS + h) * SEQ + (s + 8)) * HDIM + d)] = packh(e10, e11);
            }
        }
    }
}

// Fused Q/K/V projection: blockIdx.z selects which projection.
__global__ __launch_bounds__(256)
void qkv_proj(const float* __restrict__ bq, const float* __restrict__ bk,
              const float* __restrict__ bv) {
    const int z = blockIdx.z;
    const float* bias = (z == 0) ? bq : (z == 1) ? bk : bv;
    __half* C         = (z == 0) ? g_q : (z == 1) ? g_k : g_v;
    gemm_core<true>(g_xh, g_wh + (size_t)z * EMBED * EMBED, bias, C);
}

__global__ __launch_bounds__(256)
void out_proj(const float* __restrict__ bo, float* __restrict__ out) {
    gemm_core<false>(g_o, g_wh + (size_t)3 * EMBED * EMBED, bo, out);
}

// ---------------------------------------------------------------------------
// Flash attention, FP16 mma. Q,K,V: [B*H,S,64] fp16, O: [B,S,E] fp16.
// 128 threads = 4 warps; warp w owns 32 query rows (2 m-frags). KV tile = 64.
// cp.async double-buffered K/V; P stays entirely in registers (QK C-frag
// layout == PV A-frag layout).
// ---------------------------------------------------------------------------
__global__ __launch_bounds__(128)
void flash_mma(const __half* __restrict__ Q, const __half* __restrict__ K,
               const __half* __restrict__ V, __half* __restrict__ O) {
    __shared__ uint32_t sk[2][64][36];    // [buf][kv][dpair]
    __shared__ uint32_t sv[2][64][36];    // [buf][kv][dpair]

    const int t    = threadIdx.x;
    const int lane = t & 31;
    const int w    = t >> 5;
    const int bh   = blockIdx.y;
    const int qt   = blockIdx.x;
    const int r    = lane >> 2;
    const int cc   = lane & 3;

    const uint32_t b_loff = ((((lane & 7) + ((lane >> 4) * 8)) * 36) + (((lane >> 3) & 1) * 4)) * 4;
    const uint32_t t_loff = (((lane & 15) * 36) + ((lane >> 4) * 4)) * 4;
    const uint32_t skb = sptr(&sk[0][0][0]) + b_loff;
    const uint32_t svb = sptr(&sv[0][0][0]) + t_loff;
    const uint32_t BUFB = 64 * 36 * 4;

    const int lrow = t >> 1;          // 0..63
    const int lw16 = (t & 1) * 16;    // word offset {0,16}: 32 halves per thread
    const __half* kbase = K + ((size_t)bh * SEQ + lrow) * HDIM + lw16 * 2;
    const __half* vbase = V + ((size_t)bh * SEQ + lrow) * HDIM + lw16 * 2;
    const uint32_t kdst = sptr(&sk[0][lrow][lw16]);
    const uint32_t vdst = sptr(&sv[0][lrow][lw16]);

    // Q fragments pre-scaled by SC = (1/8)*log2(e)
    const float SC = 0.18033688011112042f;
    const __half2 sc2 = __floats2half2_rn(SC, SC);
    uint32_t qf[2][4][4];
    const __half* qb = Q + ((size_t)bh * SEQ + qt * 128 + w * 32) * HDIM;
    #pragma unroll
    for (int mi = 0; mi < 2; ++mi) {
        #pragma unroll
        for (int kf = 0; kf < 4; ++kf) {
            int row0 = mi * 16 + r;
            uint32_t u0 = *(const uint32_t*)&qb[(size_t)row0 * HDIM + kf * 16 + cc * 2];
            uint32_t u1 = *(const uint32_t*)&qb[(size_t)(row0 + 8) * HDIM + kf * 16 + cc * 2];
            uint32_t u2 = *(const uint32_t*)&qb[(size_t)row0 * HDIM + kf * 16 + 8 + cc * 2];
            uint32_t u3 = *(const uint32_t*)&qb[(size_t)(row0 + 8) * HDIM + kf * 16 + 8 + cc * 2];
            __half2 h0 = __hmul2(*(__half2*)&u0, sc2);
            __half2 h1 = __hmul2(*(__half2*)&u1, sc2);
            __half2 h2 = __hmul2(*(__half2*)&u2, sc2);
            __half2 h3 = __hmul2(*(__half2*)&u3, sc2);
            qf[mi][kf][0] = *(uint32_t*)&h0;
            qf[mi][kf][1] = *(uint32_t*)&h1;
            qf[mi][kf][2] = *(uint32_t*)&h2;
            qf[mi][kf][3] = *(uint32_t*)&h3;
        }
    }

    float o[2][8][4];
    #pragma unroll
    for (int mi = 0; mi < 2; ++mi)
        #pragma unroll
        for (int nf = 0; nf < 8; ++nf)
            #pragma unroll
            for (int j = 0; j < 4; ++j) o[mi][nf][j] = 0.0f;
    float m_i[2][2] = {{-1e30f, -1e30f}, {-1e30f, -1e30f}};   // log2 domain
    float l_i[2][2] = {{0.0f, 0.0f}, {0.0f, 0.0f}};

    // prologue: issue tile 0
    {
        cpasync16(kdst, kbase);
        cpasync16(kdst + 16, kbase + 8);
        cpasync16(kdst + 32, kbase + 16);
        cpasync16(kdst + 48, kbase + 24);
        cpasync16(vdst, vbase);
        cpasync16(vdst + 16, vbase + 8);
        cpasync16(vdst + 32, vbase + 16);
        cpasync16(vdst + 48, vbase + 24);
        cp_commit();
    }

    const int NT = SEQ / 64;
    #pragma unroll 1
    for (int kt = 0; kt < NT; ++kt) {
        const int buf = kt & 1;
        if (kt < NT - 1) {
            const size_t goff = (size_t)(kt + 1) * 64 * HDIM;
            const uint32_t boff = (buf ^ 1) * BUFB;
            cpasync16(kdst + boff, kbase + goff);
            cpasync16(kdst + boff + 16, kbase + goff + 8);
            cpasync16(kdst + boff + 32, kbase + goff + 16);
            cpasync16(kdst + boff + 48, kbase + goff + 24);
            cpasync16(vdst + boff, vbase + goff);
            cpasync16(vdst + boff + 16, vbase + goff + 8);
            cpasync16(vdst + boff + 32, vbase + goff + 16);
            cpasync16(vdst + boff + 48, vbase + goff + 24);
            cp_commit();
            cp_wait<1>();
        } else {
            cp_wait<0>();
        }
        __syncthreads();

        // S = Q @ K^T : 32 q rows x 64 kv cols per warp
        float s[2][8][4];
        #pragma unroll
        for (int mi = 0; mi < 2; ++mi)
            #pragma unroll
            for (int nf = 0; nf < 8; ++nf)
                #pragma unroll
                for (int j = 0; j < 4; ++j) s[mi][nf][j] = 0.0f;

        const uint32_t skw = skb + buf * BUFB;
        #pragma unroll
        for (int kf = 0; kf < 4; ++kf) {
            #pragma unroll
            for (int nfp = 0; nfp < 4; ++nfp) {
                uint32_t bb[4];
                ldsm4(bb, skw + (uint32_t)(nfp * 16 * 36) * 4 + kf * 32);
                #pragma unroll
                for (int mi = 0; mi < 2; ++mi) {
                    mma_f16(s[mi][2 * nfp],     qf[mi][kf], &bb[0]);
                    mma_f16(s[mi][2 * nfp + 1], qf[mi][kf], &bb[2]);
                }
            }
        }

        // Online softmax (log2 domain; scale already folded into Q) + pack P
        uint32_t pf[2][4][4];
        #pragma unroll
        for (int mi = 0; mi < 2; ++mi) {
            float mx0 = -1e30f, mx1 = -1e30f;
            #pragma unroll
            for (int nf = 0; nf < 8; ++nf) {
                mx0 = fmaxf(mx0, fmaxf(s[mi][nf][0], s[mi][nf][1]));
                mx1 = fmaxf(mx1, fmaxf(s[mi][nf][2], s[mi][nf][3]));
            }
            mx0 = fmaxf(mx0, __shfl_xor_sync(0xffffffffu, mx0, 1));
            mx0 = fmaxf(mx0, __shfl_xor_sync(0xffffffffu, mx0, 2));
            mx1 = fmaxf(mx1, __shfl_xor_sync(0xffffffffu, mx1, 1));
            mx1 = fmaxf(mx1, __shfl_xor_sync(0xffffffffu, mx1, 2));

            float mn0 = fmaxf(m_i[mi][0], mx0);
            float mn1 = fmaxf(m_i[mi][1], mx1);
            float corr0 = fexp2(m_i[mi][0] - mn0);
            float corr1 = fexp2(m_i[mi][1] - mn1);

            float rs0 = 0.0f, rs1 = 0.0f;
            #pragma unroll
            for (int nf = 0; nf < 8; ++nf) {
                s[mi][nf][0] = fexp2(s[mi][nf][0] - mn0);
                s[mi][nf][1] = fexp2(s[mi][nf][1] - mn0);
                s[mi][nf][2] = fexp2(s[mi][nf][2] - mn1);
                s[mi][nf][3] = fexp2(s[mi][nf][3] - mn1);
                rs0 += s[mi][nf][0] + s[mi][nf][1];
                rs1 += s[mi][nf][2] + s[mi][nf][3];
            }
            rs0 += __shfl_xor_sync(0xffffffffu, rs0, 1);
            rs0 += __shfl_xor_sync(0xffffffffu, rs0, 2);
            rs1 += __shfl_xor_sync(0xffffffffu, rs1, 1);
            rs1 += __shfl_xor_sync(0xffffffffu, rs1, 2);

            l_i[mi][0] = l_i[mi][0] * corr0 + rs0;
            l_i[mi][1] = l_i[mi][1] * corr1 + rs1;
            m_i[mi][0] = mn0;
            m_i[mi][1] = mn1;

            #pragma unroll
            for (int nf = 0; nf < 8; ++nf) {
                o[mi][nf][0] *= corr0; o[mi][nf][1] *= corr0;
                o[mi][nf][2] *= corr1; o[mi][nf][3] *= corr1;
            }

            // pack P into A-fragments (C-frag of QK == A-frag of PV)
            #pragma unroll
            for (int kf = 0; kf < 4; ++kf) {
                pf[mi][kf][0] = packh(s[mi][2 * kf][0],     s[mi][2 * kf][1]);
                pf[mi][kf][1] = packh(s[mi][2 * kf][2],     s[mi][2 * kf][3]);
                pf[mi][kf][2] = packh(s[mi][2 * kf + 1][0], s[mi][2 * kf + 1][1]);
                pf[mi][kf][3] = packh(s[mi][2 * kf + 1][2], s[mi][2 * kf + 1][3]);
            }
        }

        // O += P @ V  (row-major V tile, B-frags via ldmatrix.trans)
        const uint32_t svw = svb + buf * BUFB;
        #pragma unroll
        for (int kf = 0; kf < 4; ++kf) {
            #pragma unroll
            for (int nfp = 0; nfp < 4; ++nfp) {
                uint32_t bb[4];
                ldsm4t(bb, svw + (uint32_t)(kf * 16 * 36) * 4 + nfp * 32);
                #pragma unroll
                for (int mi = 0; mi < 2; ++mi) {
                    mma_f16(o[mi][2 * nfp],     pf[mi][kf], &bb[0]);
                    mma_f16(o[mi][2 * nfp + 1], pf[mi][kf], &bb[2]);
                }
            }
        }
        __syncthreads();   // all warps done with this buffer before it is refilled
    }

    // Normalize + store fp16 into [B, S, E]
    int bz = bh >> 3, h = bh & 7;
    #pragma unroll
    for (int mi = 0; mi < 2; ++mi) {
        float inv0 = 1.0f / l_i[mi][0];
        float inv1 = 1.0f / l_i[mi][1];
        int row0 = qt * 128 + w * 32 + mi * 16 + r;
        __half* op0 = O + ((size_t)bz * SEQ + row0) * EMBED + h * HDIM;
        __half* op1 = O + ((size_t)bz * SEQ + row0 + 8) * EMBED + h * HDIM;
        #pragma unroll
        for (int nf = 0; nf < 8; ++nf) {
            *(uint32_t*)(op0 + nf * 8 + 2 * cc) = packh(o[mi][nf][0] * inv0, o[mi][nf][1] * inv0);
            *(uint32_t*)(op1 + nf * 8 + 2 * cc) = packh(o[mi][nf][2] * inv1, o[mi][nf][3] * inv1);
        }
    }
}

extern "C" void kernel_launch(void* const* d_in, const int* in_sizes, int n_in,
                              void* d_out, int out_size) {
    const float* x  = (const float*)d_in[0];
    const float* Wq = (const float*)d_in[1];
    const float* bq = (const float*)d_in[2];
    const float* Wk = (const float*)d_in[3];
    const float* bk = (const float*)d_in[4];
    const float* Wv = (const float*)d_in[5];
    const float* bv = (const float*)d_in[6];
    const float* Wo = (const float*)d_in[7];
    const float* bo = (const float*)d_in[8];
    float* out = (float*)d_out;

    __half *gq, *gk, *gv, *go;
    cudaGetSymbolAddress((void**)&gq, g_q);
    cudaGetSymbolAddress((void**)&gk, g_k);
    cudaGetSymbolAddress((void**)&gv, g_v);
    cudaGetSymbolAddress((void**)&go, g_o);

    const int XC = MTOT * EMBED / 4;
    const int WC = EMBED * EMBED / 4;
    convert_f2h<<<(XC + 4 * WC) / 256, 256>>>(x, Wq, Wk, Wv, Wo);

    dim3 gridP(EMBED / 128, MTOT / 128, 3);   // (4, 64, 3)
    qkv_proj<<<gridP, 256>>>(bq, bk, bv);

    dim3 gridA(SEQ / 128, BATCH * NHEADS);    // (16, 32)
    flash_mma<<<gridA, 128>>>(gq, gk, gv, go);

    dim3 gridO(EMBED / 128, MTOT / 128);      // (4, 64)
    out_proj<<<gridO, 256>>>(bo, out);
}

// round 9
// speedup vs baseline: 1.0147x; 1.0147x over previous
#include <cuda_runtime.h>
#include <cuda_fp16.h>
#include <math.h>
#include <stdint.h>

#define EMBED  512
#define NHEADS 8
#define HDIM   64
#define BATCH  4
#define SEQ    2048
#define MTOT   (BATCH*SEQ)   // 8192

// Scratch (device globals — no runtime allocation)
__device__ __half g_xh[MTOT*EMBED];             // x in fp16
__device__ __half g_wh[4*EMBED*EMBED];          // Wq,Wk,Wv,Wo in fp16
__device__ __half g_q[BATCH*NHEADS*SEQ*HDIM];   // [B,H,S,D] fp16
__device__ __half g_k[BATCH*NHEADS*SEQ*HDIM];   // [B,H,S,D] fp16
__device__ __half g_v[BATCH*NHEADS*SEQ*HDIM];   // [B,H,S,D] fp16
__device__ __half g_o[BATCH*SEQ*EMBED];         // [B,S,E] fp16

__device__ __forceinline__ float gelu_f(float x) {
    return 0.5f * x * (1.0f + erff(x * 0.70710678118654752440f));
}

__device__ __forceinline__ uint32_t packh(float a, float b) {
    __half2 h = __floats2half2_rn(a, b);
    return *(uint32_t*)&h;
}

__device__ __forceinline__ float fexp2(float x) {
    float y;
    asm("ex2.approx.ftz.f32 %0, %1;" : "=f"(y) : "f"(x));
    return y;
}

__device__ __forceinline__ uint32_t sptr(const void* p) {
    return (uint32_t)__cvta_generic_to_shared(p);
}

__device__ __forceinline__ void cpasync16(uint32_t dst, const void* src) {
    asm volatile("cp.async.ca.shared.global [%0], [%1], 16;" :: "r"(dst), "l"(src));
}
__device__ __forceinline__ void cp_commit() {
    asm volatile("cp.async.commit_group;");
}
template<int N>
__device__ __forceinline__ void cp_wait() {
    asm volatile("cp.async.wait_group %0;" :: "n"(N));
}

__device__ __forceinline__ void mma_f16(float c[4], const uint32_t a[4], const uint32_t b[2]) {
    asm volatile(
        "mma.sync.aligned.m16n8k16.row.col.f32.f16.f16.f32 "
        "{%0,%1,%2,%3},{%4,%5,%6,%7},{%8,%9},{%0,%1,%2,%3};"
        : "+f"(c[0]), "+f"(c[1]), "+f"(c[2]), "+f"(c[3])
        : "r"(a[0]), "r"(a[1]), "r"(a[2]), "r"(a[3]), "r"(b[0]), "r"(b[1]));
}

__device__ __forceinline__ void ldsm4(uint32_t r[4], uint32_t saddr) {
    asm volatile("ldmatrix.sync.aligned.m8n8.x4.shared.b16 {%0,%1,%2,%3}, [%4];"
                 : "=r"(r[0]), "=r"(r[1]), "=r"(r[2]), "=r"(r[3]) : "r"(saddr));
}

__device__ __forceinline__ void ldsm4t(uint32_t r[4], uint32_t saddr) {
    asm volatile("ldmatrix.sync.aligned.m8n8.x4.trans.shared.b16 {%0,%1,%2,%3}, [%4];"
                 : "=r"(r[0]), "=r"(r[1]), "=r"(r[2]), "=r"(r[3]) : "r"(saddr));
}

// ---------------------------------------------------------------------------
// Convert x and all four weight matrices to fp16 (one memory-bound pass).
// ---------------------------------------------------------------------------
__global__ __launch_bounds__(256)
void convert_f2h(const float* __restrict__ x,
                 const float* __restrict__ Wq, const float* __restrict__ Wk,
                 const float* __restrict__ Wv, const float* __restrict__ Wo) {
    const int XC = MTOT * EMBED / 4;
    const int WC = EMBED * EMBED / 4;
    int i = blockIdx.x * 256 + threadIdx.x;
    float4 v;
    uint2* dst;
    if (i < XC) {
        v = ((const float4*)x)[i];
        dst = (uint2*)g_xh + i;
    } else {
        int j = i - XC;
        int w = j / WC, off = j - w * WC;
        const float* Ws = (w == 0) ? Wq : (w == 1) ? Wk : (w == 2) ? Wv : Wo;
        v = ((const float4*)Ws)[off];
        dst = (uint2*)g_wh + j;
    }
    uint2 p;
    p.x = packh(v.x, v.y);
    p.y = packh(v.z, v.w);
    *dst = p;
}

// ---------------------------------------------------------------------------
// GEMM core: C = gelu(A @ W^T + bias). A,W fp16. Block tile 128x128, 8 warps
// (2m x 4n), warp tile 64x32, BK=32, 3-stage cp.async pipeline, 1 sync/iter.
// Dynamic smem: 3 stages x (A 10240B + W 10240B) = 61440B.
// ---------------------------------------------------------------------------
#define G_STB   20480u           // stage stride bytes
#define G_WOFF  10240u           // W offset within stage

template<bool OHALF>
__device__ __forceinline__ void gemm_core(const __half* __restrict__ A,
                                          const __half* __restrict__ W,
                                          const float* __restrict__ bias, void* Cout) {
    extern __shared__ __align__(16) uint32_t dynsmem[];
    const uint32_t base = sptr(dynsmem);

    const int t    = threadIdx.x;
    const int lane = t & 31;
    const int warp = t >> 5;
    const int wm   = warp >> 2;
    const int wn   = warp & 3;
    const int m0   = blockIdx.y * 128;
    const int n0   = blockIdx.x * 128;
    const int r    = lane >> 2;
    const int cc   = lane & 3;

    const int lrow = t >> 1;          // 0..127
    const int lw   = (t & 1) * 8;     // word offset {0, 8}

    const uint32_t a_loff = (((lane & 15) * 20) + ((lane >> 4) * 4)) * 4;
    const uint32_t b_loff = ((((lane & 7) + ((lane >> 4) * 8)) * 20) + (((lane >> 3) & 1) * 4)) * 4;
    const uint32_t as_w = base + (uint32_t)(wm * 64 * 20) * 4 + a_loff;
    const uint32_t ws_w = base + G_WOFF + (uint32_t)(wn * 32 * 20) * 4 + b_loff;

    const __half* abase = A + (size_t)(m0 + lrow) * EMBED + lw * 2;
    const __half* wbase = W + (size_t)(n0 + lrow) * EMBED + lw * 2;
    const uint32_t adst = base + (uint32_t)(lrow * 20 + lw) * 4;
    const uint32_t wdst = adst + G_WOFF;

    float acc[4][4][4];
    #pragma unroll
    for (int mi = 0; mi < 4; ++mi)
        #pragma unroll
        for (int ni = 0; ni < 4; ++ni)
            #pragma unroll
            for (int j = 0; j < 4; ++j) acc[mi][ni][j] = 0.0f;

    // prologue: issue tiles 0, 1
    #pragma unroll
    for (int tile = 0; tile < 2; ++tile) {
        const uint32_t boff = tile * G_STB;
        const int k0 = tile * 32;
        cpasync16(adst + boff, abase + k0);
        cpasync16(adst + boff + 16, abase + k0 + 8);
        cpasync16(wdst + boff, wbase + k0);
        cpasync16(wdst + boff + 16, wbase + k0 + 8);
        cp_commit();
    }

    #pragma unroll 1
    for (int i = 0; i < 16; ++i) {
        if (i < 15) cp_wait<1>(); else cp_wait<0>();
        __syncthreads();

        // issue tile i+2 into the buffer consumed at i-1 (safe past this sync)
        if (i + 2 < 16) {
            const uint32_t boff = ((i + 2) % 3) * G_STB;
            const int k0 = (i + 2) * 32;
            cpasync16(adst + boff, abase + k0);
            cpasync16(adst + boff + 16, abase + k0 + 8);
            cpasync16(wdst + boff, wbase + k0);
            cpasync16(wdst + boff + 16, wbase + k0 + 8);
            cp_commit();
        }

        const uint32_t sb = (uint32_t)(i % 3) * G_STB;
        const uint32_t aw = as_w + sb;
        const uint32_t ww = ws_w + sb;
        #pragma unroll
        for (int ks = 0; ks < 2; ++ks) {
            uint32_t a[4][4], b[2][4];
            #pragma unroll
            for (int mi = 0; mi < 4; ++mi)
                ldsm4(a[mi], aw + (uint32_t)(mi * 16 * 20) * 4 + ks * 32);
            #pragma unroll
            for (int np = 0; np < 2; ++np)
                ldsm4(b[np], ww + (uint32_t)(np * 16 * 20) * 4 + ks * 32);
            #pragma unroll
            for (int mi = 0; mi < 4; ++mi)
                #pragma unroll
                for (int np = 0; np < 2; ++np) {
                    mma_f16(acc[mi][2 * np],     a[mi], &b[np][0]);
                    mma_f16(acc[mi][2 * np + 1], a[mi], &b[np][2]);
                }
        }
    }

    // Epilogue: bias + gelu, store
    #pragma unroll
    for (int mi = 0; mi < 4; ++mi) {
        #pragma unroll
        for (int ni = 0; ni < 4; ++ni) {
            int row = m0 + wm * 64 + mi * 16 + r;
            int col = n0 + wn * 32 + ni * 8 + 2 * cc;
            float b0 = bias[col], b1 = bias[col + 1];
            float e00 = gelu_f(acc[mi][ni][0] + b0);
            float e01 = gelu_f(acc[mi][ni][1] + b1);
            float e10 = gelu_f(acc[mi][ni][2] + b0);
            float e11 = gelu_f(acc[mi][ni][3] + b1);
            if (!OHALF) {
                float* C = (float*)Cout;
                float2 v0 = {e00, e01}, v1 = {e10, e11};
                *(float2*)(C + (size_t)row * EMBED + col)       = v0;
                *(float2*)(C + (size_t)(row + 8) * EMBED + col) = v1;
            } else {
                __half* C = (__half*)Cout;
                int bz = row >> 11, s = row & (SEQ - 1);
                int h = col >> 6, d = col & 63;
                *(uint32_t*)&C[(((size_t)(bz * NHEADS + h) * SEQ + s) * HDIM + d)]       = packh(e00, e01);
                *(uint32_t*)&C[(((size_t)(bz * NHEADS + h) * SEQ + (s + 8)) * HDIM + d)] = packh(e10, e11);
            }
        }
    }
}

__global__ __launch_bounds__(256)
void qkv_proj(const float* __restrict__ bq, const float* __restrict__ bk,
              const float* __restrict__ bv) {
    const int z = blockIdx.z;
    const float* bias = (z == 0) ? bq : (z == 1) ? bk : bv;
    __half* C         = (z == 0) ? g_q : (z == 1) ? g_k : g_v;
    gemm_core<true>(g_xh, g_wh + (size_t)z * EMBED * EMBED, bias, C);
}

__global__ __launch_bounds__(256)
void out_proj(const float* __restrict__ bo, float* __restrict__ out) {
    gemm_core<false>(g_o, g_wh + (size_t)3 * EMBED * EMBED, bo, out);
}

// ---------------------------------------------------------------------------
// Flash attention. Q,K,V: [B*H,S,64] fp16, O: [B,S,E] fp16.
// 128 threads = 4 warps; warp owns 32 q rows. KV tile = 64.
// 3-stage cp.async K/V pipeline, ONE sync per tile; P entirely in registers.
// Dynamic smem: 3 stages x (K 9216B + V 9216B) = 55296B.
// ---------------------------------------------------------------------------
#define F_STB   18432u
#define F_VOFF  9216u

__global__ __launch_bounds__(128)
void flash_mma(const __half* __restrict__ Q, const __half* __restrict__ K,
               const __half* __restrict__ V, __half* __restrict__ O) {
    extern __shared__ __align__(16) uint32_t dynsmem[];
    const uint32_t base = sptr(dynsmem);

    const int t    = threadIdx.x;
    const int lane = t & 31;
    const int w    = t >> 5;
    const int bh   = blockIdx.y;
    const int qt   = blockIdx.x;
    const int r    = lane >> 2;
    const int cc   = lane & 3;

    const uint32_t b_loff = ((((lane & 7) + ((lane >> 4) * 8)) * 36) + (((lane >> 3) & 1) * 4)) * 4;
    const uint32_t t_loff = (((lane & 15) * 36) + ((lane >> 4) * 4)) * 4;
    const uint32_t skb = base + b_loff;
    const uint32_t svb = base + F_VOFF + t_loff;

    const int lrow = t >> 1;          // 0..63
    const int lw16 = (t & 1) * 16;    // word offset {0,16}
    const __half* kbase = K + ((size_t)bh * SEQ + lrow) * HDIM + lw16 * 2;
    const __half* vbase = V + ((size_t)bh * SEQ + lrow) * HDIM + lw16 * 2;
    const uint32_t kdst = base + (uint32_t)(lrow * 36 + lw16) * 4;
    const uint32_t vdst = kdst + F_VOFF;

    // Q fragments pre-scaled by SC = (1/8)*log2(e)
    const float SC = 0.18033688011112042f;
    const __half2 sc2 = __floats2half2_rn(SC, SC);
    uint32_t qf[2][4][4];
    const __half* qb = Q + ((size_t)bh * SEQ + qt * 128 + w * 32) * HDIM;
    #pragma unroll
    for (int mi = 0; mi < 2; ++mi) {
        #pragma unroll
        for (int kf = 0; kf < 4; ++kf) {
            int row0 = mi * 16 + r;
            uint32_t u0 = *(const uint32_t*)&qb[(size_t)row0 * HDIM + kf * 16 + cc * 2];
            uint32_t u1 = *(const uint32_t*)&qb[(size_t)(row0 + 8) * HDIM + kf * 16 + cc * 2];
            uint32_t u2 = *(const uint32_t*)&qb[(size_t)row0 * HDIM + kf * 16 + 8 + cc * 2];
            uint32_t u3 = *(const uint32_t*)&qb[(size_t)(row0 + 8) * HDIM + kf * 16 + 8 + cc * 2];
            __half2 h0 = __hmul2(*(__half2*)&u0, sc2);
            __half2 h1 = __hmul2(*(__half2*)&u1, sc2);
            __half2 h2 = __hmul2(*(__half2*)&u2, sc2);
            __half2 h3 = __hmul2(*(__half2*)&u3, sc2);
            qf[mi][kf][0] = *(uint32_t*)&h0;
            qf[mi][kf][1] = *(uint32_t*)&h1;
            qf[mi][kf][2] = *(uint32_t*)&h2;
            qf[mi][kf][3] = *(uint32_t*)&h3;
        }
    }

    float o[2][8][4];
    #pragma unroll
    for (int mi = 0; mi < 2; ++mi)
        #pragma unroll
        for (int nf = 0; nf < 8; ++nf)
            #pragma unroll
            for (int j = 0; j < 4; ++j) o[mi][nf][j] = 0.0f;
    float m_i[2][2] = {{-1e30f, -1e30f}, {-1e30f, -1e30f}};
    float l_i[2][2] = {{0.0f, 0.0f}, {0.0f, 0.0f}};

    // prologue: issue tiles 0, 1
    #pragma unroll
    for (int tile = 0; tile < 2; ++tile) {
        const uint32_t boff = tile * F_STB;
        const size_t goff = (size_t)tile * 64 * HDIM;
        cpasync16(kdst + boff,      kbase + goff);
        cpasync16(kdst + boff + 16, kbase + goff + 8);
        cpasync16(kdst + boff + 32, kbase + goff + 16);
        cpasync16(kdst + boff + 48, kbase + goff + 24);
        cpasync16(vdst + boff,      vbase + goff);
        cpasync16(vdst + boff + 16, vbase + goff + 8);
        cpasync16(vdst + boff + 32, vbase + goff + 16);
        cpasync16(vdst + boff + 48, vbase + goff + 24);
        cp_commit();
    }

    const int NT = SEQ / 64;
    #pragma unroll 1
    for (int kt = 0; kt < NT; ++kt) {
        if (kt < NT - 1) cp_wait<1>(); else cp_wait<0>();
        __syncthreads();

        // refill buffer consumed at kt-1 (all warps are past the sync)
        if (kt + 2 < NT) {
            const uint32_t boff = ((kt + 2) % 3) * F_STB;
            const size_t goff = (size_t)(kt + 2) * 64 * HDIM;
            cpasync16(kdst + boff,      kbase + goff);
            cpasync16(kdst + boff + 16, kbase + goff + 8);
            cpasync16(kdst + boff + 32, kbase + goff + 16);
            cpasync16(kdst + boff + 48, kbase + goff + 24);
            cpasync16(vdst + boff,      vbase + goff);
            cpasync16(vdst + boff + 16, vbase + goff + 8);
            cpasync16(vdst + boff + 32, vbase + goff + 16);
            cpasync16(vdst + boff + 48, vbase + goff + 24);
            cp_commit();
        }

        const uint32_t sb = (uint32_t)(kt % 3) * F_STB;

        // S = Q @ K^T
        float s[2][8][4];
        #pragma unroll
        for (int mi = 0; mi < 2; ++mi)
            #pragma unroll
            for (int nf = 0; nf < 8; ++nf)
                #pragma unroll
                for (int j = 0; j < 4; ++j) s[mi][nf][j] = 0.0f;

        const uint32_t skw = skb + sb;
        #pragma unroll
        for (int kf = 0; kf < 4; ++kf) {
            #pragma unroll
            for (int nfp = 0; nfp < 4; ++nfp) {
                uint32_t bb[4];
                ldsm4(bb, skw + (uint32_t)(nfp * 16 * 36) * 4 + kf * 32);
                #pragma unroll
                for (int mi = 0; mi < 2; ++mi) {
                    mma_f16(s[mi][2 * nfp],     qf[mi][kf], &bb[0]);
                    mma_f16(s[mi][2 * nfp + 1], qf[mi][kf], &bb[2]);
                }
            }
        }

        // Online softmax (log2 domain) + pack P into registers
        uint32_t pf[2][4][4];
        #pragma unroll
        for (int mi = 0; mi < 2; ++mi) {
            float mx0 = -1e30f, mx1 = -1e30f;
            #pragma unroll
            for (int nf = 0; nf < 8; ++nf) {
                mx0 = fmaxf(mx0, fmaxf(s[mi][nf][0], s[mi][nf][1]));
                mx1 = fmaxf(mx1, fmaxf(s[mi][nf][2], s[mi][nf][3]));
            }
            mx0 = fmaxf(mx0, __shfl_xor_sync(0xffffffffu, mx0, 1));
            mx0 = fmaxf(mx0, __shfl_xor_sync(0xffffffffu, mx0, 2));
            mx1 = fmaxf(mx1, __shfl_xor_sync(0xffffffffu, mx1, 1));
            mx1 = fmaxf(mx1, __shfl_xor_sync(0xffffffffu, mx1, 2));

            float mn0 = fmaxf(m_i[mi][0], mx0);
            float mn1 = fmaxf(m_i[mi][1], mx1);
            float corr0 = fexp2(m_i[mi][0] - mn0);
            float corr1 = fexp2(m_i[mi][1] - mn1);

            float rs0 = 0.0f, rs1 = 0.0f;
            #pragma unroll
            for (int nf = 0; nf < 8; ++nf) {
                s[mi][nf][0] = fexp2(s[mi][nf][0] - mn0);
                s[mi][nf][1] = fexp2(s[mi][nf][1] - mn0);
                s[mi][nf][2] = fexp2(s[mi][nf][2] - mn1);
                s[mi][nf][3] = fexp2(s[mi][nf][3] - mn1);
                rs0 += s[mi][nf][0] + s[mi][nf][1];
                rs1 += s[mi][nf][2] + s[mi][nf][3];
            }
            rs0 += __shfl_xor_sync(0xffffffffu, rs0, 1);
            rs0 += __shfl_xor_sync(0xffffffffu, rs0, 2);
            rs1 += __shfl_xor_sync(0xffffffffu, rs1, 1);
            rs1 += __shfl_xor_sync(0xffffffffu, rs1, 2);

            l_i[mi][0] = l_i[mi][0] * corr0 + rs0;
            l_i[mi][1] = l_i[mi][1] * corr1 + rs1;
            m_i[mi][0] = mn0;
            m_i[mi][1] = mn1;

            #pragma unroll
            for (int nf = 0; nf < 8; ++nf) {
                o[mi][nf][0] *= corr0; o[mi][nf][1] *= corr0;
                o[mi][nf][2] *= corr1; o[mi][nf][3] *= corr1;
            }

            #pragma unroll
            for (int kf = 0; kf < 4; ++kf) {
                pf[mi][kf][0] = packh(s[mi][2 * kf][0],     s[mi][2 * kf][1]);
                pf[mi][kf][1] = packh(s[mi][2 * kf][2],     s[mi][2 * kf][3]);
                pf[mi][kf][2] = packh(s[mi][2 * kf + 1][0], s[mi][2 * kf + 1][1]);
                pf[mi][kf][3] = packh(s[mi][2 * kf + 1][2], s[mi][2 * kf + 1][3]);
            }
        }

        // O += P @ V  (row-major V tile, B-frags via ldmatrix.trans)
        const uint32_t svw = svb + sb;
        #pragma unroll
        for (int kf = 0; kf < 4; ++kf) {
            #pragma unroll
            for (int nfp = 0; nfp < 4; ++nfp) {
                uint32_t bb[4];
                ldsm4t(bb, svw + (uint32_t)(kf * 16 * 36) * 4 + nfp * 32);
                #pragma unroll
                for (int mi = 0; mi < 2; ++mi) {
                    mma_f16(o[mi][2 * nfp],     pf[mi][kf], &bb[0]);
                    mma_f16(o[mi][2 * nfp + 1], pf[mi][kf], &bb[2]);
                }
            }
        }
    }

    // Normalize + store fp16 into [B, S, E]
    int bz = bh >> 3, h = bh & 7;
    #pragma unroll
    for (int mi = 0; mi < 2; ++mi) {
        float inv0 = 1.0f / l_i[mi][0];
        float inv1 = 1.0f / l_i[mi][1];
        int row0 = qt * 128 + w * 32 + mi * 16 + r;
        __half* op0 = O + ((size_t)bz * SEQ + row0) * EMBED + h * HDIM;
        __half* op1 = O + ((size_t)bz * SEQ + row0 + 8) * EMBED + h * HDIM;
        #pragma unroll
        for (int nf = 0; nf < 8; ++nf) {
            *(uint32_t*)(op0 + nf * 8 + 2 * cc) = packh(o[mi][nf][0] * inv0, o[mi][nf][1] * inv0);
            *(uint32_t*)(op1 + nf * 8 + 2 * cc) = packh(o[mi][nf][2] * inv1, o[mi][nf][3] * inv1);
        }
    }
}

extern "C" void kernel_launch(void* const* d_in, const int* in_sizes, int n_in,
                              void* d_out, int out_size) {
    const float* x  = (const float*)d_in[0];
    const float* Wq = (const float*)d_in[1];
    const float* bq = (const float*)d_in[2];
    const float* Wk = (const float*)d_in[3];
    const float* bk = (const float*)d_in[4];
    const float* Wv = (const float*)d_in[5];
    const float* bv = (const float*)d_in[6];
    const float* Wo = (const float*)d_in[7];
    const float* bo = (const float*)d_in[8];
    float* out = (float*)d_out;

    __half *gq, *gk, *gv, *go;
    cudaGetSymbolAddress((void**)&gq, g_q);
    cudaGetSymbolAddress((void**)&gk, g_k);
    cudaGetSymbolAddress((void**)&gv, g_v);
    cudaGetSymbolAddress((void**)&go, g_o);

    const int GEMM_SMEM  = 3 * 2 * 128 * 20 * 4;   // 61440
    const int FLASH_SMEM = 3 * 2 * 64 * 36 * 4;    // 55296
    cudaFuncSetAttribute(qkv_proj,  cudaFuncAttributeMaxDynamicSharedMemorySize, GEMM_SMEM);
    cudaFuncSetAttribute(out_proj,  cudaFuncAttributeMaxDynamicSharedMemorySize, GEMM_SMEM);
    cudaFuncSetAttribute(flash_mma, cudaFuncAttributeMaxDynamicSharedMemorySize, FLASH_SMEM);

    const int XC = MTOT * EMBED / 4;
    const int WC = EMBED * EMBED / 4;
    convert_f2h<<<(XC + 4 * WC) / 256, 256>>>(x, Wq, Wk, Wv, Wo);

    dim3 gridP(EMBED / 128, MTOT / 128, 3);   // (4, 64, 3)
    qkv_proj<<<gridP, 256, GEMM_SMEM>>>(bq, bk, bv);

    dim3 gridA(SEQ / 128, BATCH * NHEADS);    // (16, 32)
    flash_mma<<<gridA, 128, FLASH_SMEM>>>(gq, gk, gv, go);

    dim3 gridO(EMBED / 128, MTOT / 128);      // (4, 64)
    out_proj<<<gridO, 256, GEMM_SMEM>>>(bo, out);
}

// round 10
// speedup vs baseline: 1.0246x; 1.0097x over previous
#include <cuda_runtime.h>
#include <cuda_fp16.h>
#include <math.h>
#include <stdint.h>

#define EMBED  512
#define NHEADS 8
#define HDIM   64
#define BATCH  4
#define SEQ    2048
#define MTOT   (BATCH*SEQ)   // 8192

// Scratch (device globals — no runtime allocation)
__device__ __half g_xh[MTOT*EMBED];             // x in fp16
__device__ __half g_wh[4*EMBED*EMBED];          // Wq,Wk,Wv,Wo in fp16
__device__ __half g_q[BATCH*NHEADS*SEQ*HDIM];   // [B,H,S,D] fp16
__device__ __half g_k[BATCH*NHEADS*SEQ*HDIM];   // [B,H,S,D] fp16
__device__ __half g_v[BATCH*NHEADS*SEQ*HDIM];   // [B,H,S,D] fp16
__device__ __half g_o[BATCH*SEQ*EMBED];         // [B,S,E] fp16

__device__ __forceinline__ float gelu_f(float x) {
    return 0.5f * x * (1.0f + erff(x * 0.70710678118654752440f));
}

__device__ __forceinline__ uint32_t packh(float a, float b) {
    __half2 h = __floats2half2_rn(a, b);
    return *(uint32_t*)&h;
}

__device__ __forceinline__ float fexp2(float x) {
    float y;
    asm("ex2.approx.ftz.f32 %0, %1;" : "=f"(y) : "f"(x));
    return y;
}

__device__ __forceinline__ uint32_t sptr(const void* p) {
    return (uint32_t)__cvta_generic_to_shared(p);
}

__device__ __forceinline__ void cpasync16(uint32_t dst, const void* src) {
    asm volatile("cp.async.ca.shared.global [%0], [%1], 16;" :: "r"(dst), "l"(src));
}
__device__ __forceinline__ void cp_commit() {
    asm volatile("cp.async.commit_group;");
}
template<int N>
__device__ __forceinline__ void cp_wait() {
    asm volatile("cp.async.wait_group %0;" :: "n"(N));
}

__device__ __forceinline__ void mma_f16(float c[4], const uint32_t a[4], const uint32_t b[2]) {
    asm volatile(
        "mma.sync.aligned.m16n8k16.row.col.f32.f16.f16.f32 "
        "{%0,%1,%2,%3},{%4,%5,%6,%7},{%8,%9},{%0,%1,%2,%3};"
        : "+f"(c[0]), "+f"(c[1]), "+f"(c[2]), "+f"(c[3])
        : "r"(a[0]), "r"(a[1]), "r"(a[2]), "r"(a[3]), "r"(b[0]), "r"(b[1]));
}

__device__ __forceinline__ void ldsm4(uint32_t r[4], uint32_t saddr) {
    asm volatile("ldmatrix.sync.aligned.m8n8.x4.shared.b16 {%0,%1,%2,%3}, [%4];"
                 : "=r"(r[0]), "=r"(r[1]), "=r"(r[2]), "=r"(r[3]) : "r"(saddr));
}

__device__ __forceinline__ void ldsm4t(uint32_t r[4], uint32_t saddr) {
    asm volatile("ldmatrix.sync.aligned.m8n8.x4.trans.shared.b16 {%0,%1,%2,%3}, [%4];"
                 : "=r"(r[0]), "=r"(r[1]), "=r"(r[2]), "=r"(r[3]) : "r"(saddr));
}

// ---------------------------------------------------------------------------
// Convert x and all four weight matrices to fp16 (one memory-bound pass).
// ---------------------------------------------------------------------------
__global__ __launch_bounds__(256)
void convert_f2h(const float* __restrict__ x,
                 const float* __restrict__ Wq, const float* __restrict__ Wk,
                 const float* __restrict__ Wv, const float* __restrict__ Wo) {
    const int XC = MTOT * EMBED / 4;
    const int WC = EMBED * EMBED / 4;
    int i = blockIdx.x * 256 + threadIdx.x;
    float4 v;
    uint2* dst;
    if (i < XC) {
        v = ((const float4*)x)[i];
        dst = (uint2*)g_xh + i;
    } else {
        int j = i - XC;
        int w = j / WC, off = j - w * WC;
        const float* Ws = (w == 0) ? Wq : (w == 1) ? Wk : (w == 2) ? Wv : Wo;
        v = ((const float4*)Ws)[off];
        dst = (uint2*)g_wh + j;
    }
    uint2 p;
    p.x = packh(v.x, v.y);
    p.y = packh(v.z, v.w);
    *dst = p;
}

// ---------------------------------------------------------------------------
// GEMM core: C = gelu(A @ W^T + bias). A,W fp16. Block tile 128x128, 8 warps
// (2m x 4n), warp tile 64x32, BK=64, 2-stage cp.async pipeline, 1 sync/iter.
// Smem row = 64 halves (32 words) + 4 pad = 36 words (conflict-free ldmatrix).
// Dynamic smem: 2 stages x (A 18432B + W 18432B) = 73728B.
// ---------------------------------------------------------------------------
#define G_ABYTES 18432u          // 128 rows * 36 words * 4B
#define G_WOFF   G_ABYTES
#define G_STB    36864u          // stage stride bytes

template<bool OHALF>
__device__ __forceinline__ void gemm_core(const __half* __restrict__ A,
                                          const __half* __restrict__ W,
                                          const float* __restrict__ bias, void* Cout) {
    extern __shared__ __align__(16) uint32_t dynsmem[];
    const uint32_t base = sptr(dynsmem);

    const int t    = threadIdx.x;
    const int lane = t & 31;
    const int warp = t >> 5;
    const int wm   = warp >> 2;
    const int wn   = warp & 3;
    const int m0   = blockIdx.y * 128;
    const int n0   = blockIdx.x * 128;
    const int r    = lane >> 2;
    const int cc   = lane & 3;

    const int lrow = t >> 1;          // 0..127
    const int lw   = (t & 1) * 16;    // word offset {0, 16} (32 halves/thread)

    const uint32_t a_loff = (((lane & 15) * 36) + ((lane >> 4) * 4)) * 4;
    const uint32_t b_loff = ((((lane & 7) + ((lane >> 4) * 8)) * 36) + (((lane >> 3) & 1) * 4)) * 4;
    const uint32_t as_w = base + (uint32_t)(wm * 64 * 36) * 4 + a_loff;
    const uint32_t ws_w = base + G_WOFF + (uint32_t)(wn * 32 * 36) * 4 + b_loff;

    const __half* abase = A + (size_t)(m0 + lrow) * EMBED + lw * 2;
    const __half* wbase = W + (size_t)(n0 + lrow) * EMBED + lw * 2;
    const uint32_t adst = base + (uint32_t)(lrow * 36 + lw) * 4;
    const uint32_t wdst = adst + G_WOFF;

    float acc[4][4][4];
    #pragma unroll
    for (int mi = 0; mi < 4; ++mi)
        #pragma unroll
        for (int ni = 0; ni < 4; ++ni)
            #pragma unroll
            for (int j = 0; j < 4; ++j) acc[mi][ni][j] = 0.0f;

    // prologue: issue tile 0
    #pragma unroll
    for (int j = 0; j < 4; ++j) {
        cpasync16(adst + j * 16, abase + j * 8);
        cpasync16(wdst + j * 16, wbase + j * 8);
    }
    cp_commit();

    #pragma unroll 1
    for (int i = 0; i < 8; ++i) {
        cp_wait<0>();
        __syncthreads();

        // issue tile i+1 into the other buffer (consumed at i-1, safe past sync)
        if (i + 1 < 8) {
            const uint32_t boff = ((i + 1) & 1) * G_STB;
            const int k0 = (i + 1) * 64;
            #pragma unroll
            for (int j = 0; j < 4; ++j) {
                cpasync16(adst + boff + j * 16, abase + k0 + j * 8);
                cpasync16(wdst + boff + j * 16, wbase + k0 + j * 8);
            }
            cp_commit();
        }

        const uint32_t sb = (uint32_t)(i & 1) * G_STB;
        const uint32_t aw = as_w + sb;
        const uint32_t ww = ws_w + sb;
        #pragma unroll
        for (int ks = 0; ks < 4; ++ks) {
            uint32_t a[4][4], b[2][4];
            #pragma unroll
            for (int mi = 0; mi < 4; ++mi)
                ldsm4(a[mi], aw + (uint32_t)(mi * 16 * 36) * 4 + ks * 32);
            #pragma unroll
            for (int np = 0; np < 2; ++np)
                ldsm4(b[np], ww + (uint32_t)(np * 16 * 36) * 4 + ks * 32);
            #pragma unroll
            for (int mi = 0; mi < 4; ++mi)
                #pragma unroll
                for (int np = 0; np < 2; ++np) {
                    mma_f16(acc[mi][2 * np],     a[mi], &b[np][0]);
                    mma_f16(acc[mi][2 * np + 1], a[mi], &b[np][2]);
                }
        }
    }

    // Epilogue: bias + gelu, store
    #pragma unroll
    for (int mi = 0; mi < 4; ++mi) {
        #pragma unroll
        for (int ni = 0; ni < 4; ++ni) {
            int row = m0 + wm * 64 + mi * 16 + r;
            int col = n0 + wn * 32 + ni * 8 + 2 * cc;
            float b0 = bias[col], b1 = bias[col + 1];
            float e00 = gelu_f(acc[mi][ni][0] + b0);
            float e01 = gelu_f(acc[mi][ni][1] + b1);
            float e10 = gelu_f(acc[mi][ni][2] + b0);
            float e11 = gelu_f(acc[mi][ni][3] + b1);
            if (!OHALF) {
                float* C = (float*)Cout;
                float2 v0 = {e00, e01}, v1 = {e10, e11};
                *(float2*)(C + (size_t)row * EMBED + col)       = v0;
                *(float2*)(C + (size_t)(row + 8) * EMBED + col) = v1;
            } else {
                __half* C = (__half*)Cout;
                int bz = row >> 11, s = row & (SEQ - 1);
                int h = col >> 6, d = col & 63;
                *(uint32_t*)&C[(((size_t)(bz * NHEADS + h) * SEQ + s) * HDIM + d)]       = packh(e00, e01);
                *(uint32_t*)&C[(((size_t)(bz * NHEADS + h) * SEQ + (s + 8)) * HDIM + d)] = packh(e10, e11);
            }
        }
    }
}

__global__ __launch_bounds__(256)
void qkv_proj(const float* __restrict__ bq, const float* __restrict__ bk,
              const float* __restrict__ bv) {
    const int z = blockIdx.z;
    const float* bias = (z == 0) ? bq : (z == 1) ? bk : bv;
    __half* C         = (z == 0) ? g_q : (z == 1) ? g_k : g_v;
    gemm_core<true>(g_xh, g_wh + (size_t)z * EMBED * EMBED, bias, C);
}

__global__ __launch_bounds__(256)
void out_proj(const float* __restrict__ bo, float* __restrict__ out) {
    gemm_core<false>(g_o, g_wh + (size_t)3 * EMBED * EMBED, bo, out);
}

// ---------------------------------------------------------------------------
// Flash attention. Q,K,V: [B*H,S,64] fp16, O: [B,S,E] fp16.
// 128 threads = 4 warps; warp owns 32 q rows. KV tile = 64.
// 3-stage cp.async K/V pipeline, ONE sync per tile; P entirely in registers.
// Dynamic smem: 3 stages x (K 9216B + V 9216B) = 55296B.
// ---------------------------------------------------------------------------
#define F_STB   18432u
#define F_VOFF  9216u

__global__ __launch_bounds__(128)
void flash_mma(const __half* __restrict__ Q, const __half* __restrict__ K,
               const __half* __restrict__ V, __half* __restrict__ O) {
    extern __shared__ __align__(16) uint32_t dynsmem[];
    const uint32_t base = sptr(dynsmem);

    const int t    = threadIdx.x;
    const int lane = t & 31;
    const int w    = t >> 5;
    const int bh   = blockIdx.y;
    const int qt   = blockIdx.x;
    const int r    = lane >> 2;
    const int cc   = lane & 3;

    const uint32_t b_loff = ((((lane & 7) + ((lane >> 4) * 8)) * 36) + (((lane >> 3) & 1) * 4)) * 4;
    const uint32_t t_loff = (((lane & 15) * 36) + ((lane >> 4) * 4)) * 4;
    const uint32_t skb = base + b_loff;
    const uint32_t svb = base + F_VOFF + t_loff;

    const int lrow = t >> 1;          // 0..63
    const int lw16 = (t & 1) * 16;    // word offset {0,16}
    const __half* kbase = K + ((size_t)bh * SEQ + lrow) * HDIM + lw16 * 2;
    const __half* vbase = V + ((size_t)bh * SEQ + lrow) * HDIM + lw16 * 2;
    const uint32_t kdst = base + (uint32_t)(lrow * 36 + lw16) * 4;
    const uint32_t vdst = kdst + F_VOFF;

    // Q fragments pre-scaled by SC = (1/8)*log2(e)
    const float SC = 0.18033688011112042f;
    const __half2 sc2 = __floats2half2_rn(SC, SC);
    uint32_t qf[2][4][4];
    const __half* qb = Q + ((size_t)bh * SEQ + qt * 128 + w * 32) * HDIM;
    #pragma unroll
    for (int mi = 0; mi < 2; ++mi) {
        #pragma unroll
        for (int kf = 0; kf < 4; ++kf) {
            int row0 = mi * 16 + r;
            uint32_t u0 = *(const uint32_t*)&qb[(size_t)row0 * HDIM + kf * 16 + cc * 2];
            uint32_t u1 = *(const uint32_t*)&qb[(size_t)(row0 + 8) * HDIM + kf * 16 + cc * 2];
            uint32_t u2 = *(const uint32_t*)&qb[(size_t)row0 * HDIM + kf * 16 + 8 + cc * 2];
            uint32_t u3 = *(const uint32_t*)&qb[(size_t)(row0 + 8) * HDIM + kf * 16 + 8 + cc * 2];
            __half2 h0 = __hmul2(*(__half2*)&u0, sc2);
            __half2 h1 = __hmul2(*(__half2*)&u1, sc2);
            __half2 h2 = __hmul2(*(__half2*)&u2, sc2);
            __half2 h3 = __hmul2(*(__half2*)&u3, sc2);
            qf[mi][kf][0] = *(uint32_t*)&h0;
            qf[mi][kf][1] = *(uint32_t*)&h1;
            qf[mi][kf][2] = *(uint32_t*)&h2;
            qf[mi][kf][3] = *(uint32_t*)&h3;
        }
    }

    float o[2][8][4];
    #pragma unroll
    for (int mi = 0; mi < 2; ++mi)
        #pragma unroll
        for (int nf = 0; nf < 8; ++nf)
            #pragma unroll
            for (int j = 0; j < 4; ++j) o[mi][nf][j] = 0.0f;
    float m_i[2][2] = {{-1e30f, -1e30f}, {-1e30f, -1e30f}};
    float l_i[2][2] = {{0.0f, 0.0f}, {0.0f, 0.0f}};

    // prologue: issue tiles 0, 1
    #pragma unroll
    for (int tile = 0; tile < 2; ++tile) {
        const uint32_t boff = tile * F_STB;
        const size_t goff = (size_t)tile * 64 * HDIM;
        cpasync16(kdst + boff,      kbase + goff);
        cpasync16(kdst + boff + 16, kbase + goff + 8);
        cpasync16(kdst + boff + 32, kbase + goff + 16);
        cpasync16(kdst + boff + 48, kbase + goff + 24);
        cpasync16(vdst + boff,      vbase + goff);
        cpasync16(vdst + boff + 16, vbase + goff + 8);
        cpasync16(vdst + boff + 32, vbase + goff + 16);
        cpasync16(vdst + boff + 48, vbase + goff + 24);
        cp_commit();
    }

    const int NT = SEQ / 64;
    #pragma unroll 1
    for (int kt = 0; kt < NT; ++kt) {
        if (kt < NT - 1) cp_wait<1>(); else cp_wait<0>();
        __syncthreads();

        // refill buffer consumed at kt-1 (all warps are past the sync)
        if (kt + 2 < NT) {
            const uint32_t boff = ((kt + 2) % 3) * F_STB;
            const size_t goff = (size_t)(kt + 2) * 64 * HDIM;
            cpasync16(kdst + boff,      kbase + goff);
            cpasync16(kdst + boff + 16, kbase + goff + 8);
            cpasync16(kdst + boff + 32, kbase + goff + 16);
            cpasync16(kdst + boff + 48, kbase + goff + 24);
            cpasync16(vdst + boff,      vbase + goff);
            cpasync16(vdst + boff + 16, vbase + goff + 8);
            cpasync16(vdst + boff + 32, vbase + goff + 16);
            cpasync16(vdst + boff + 48, vbase + goff + 24);
            cp_commit();
        }

        const uint32_t sb = (uint32_t)(kt % 3) * F_STB;

        // S = Q @ K^T
        float s[2][8][4];
        #pragma unroll
        for (int mi = 0; mi < 2; ++mi)
            #pragma unroll
            for (int nf = 0; nf < 8; ++nf)
                #pragma unroll
                for (int j = 0; j < 4; ++j) s[mi][nf][j] = 0.0f;

        const uint32_t skw = skb + sb;
        #pragma unroll
        for (int kf = 0; kf < 4; ++kf) {
            #pragma unroll
            for (int nfp = 0; nfp < 4; ++nfp) {
                uint32_t bb[4];
                ldsm4(bb, skw + (uint32_t)(nfp * 16 * 36) * 4 + kf * 32);
                #pragma unroll
                for (int mi = 0; mi < 2; ++mi) {
                    mma_f16(s[mi][2 * nfp],     qf[mi][kf], &bb[0]);
                    mma_f16(s[mi][2 * nfp + 1], qf[mi][kf], &bb[2]);
                }
            }
        }

        // Online softmax (log2 domain) + pack P into registers
        uint32_t pf[2][4][4];
        #pragma unroll
        for (int mi = 0; mi < 2; ++mi) {
            float mx0 = -1e30f, mx1 = -1e30f;
            #pragma unroll
            for (int nf = 0; nf < 8; ++nf) {
                mx0 = fmaxf(mx0, fmaxf(s[mi][nf][0], s[mi][nf][1]));
                mx1 = fmaxf(mx1, fmaxf(s[mi][nf][2], s[mi][nf][3]));
            }
            mx0 = fmaxf(mx0, __shfl_xor_sync(0xffffffffu, mx0, 1));
            mx0 = fmaxf(mx0, __shfl_xor_sync(0xffffffffu, mx0, 2));
            mx1 = fmaxf(mx1, __shfl_xor_sync(0xffffffffu, mx1, 1));
            mx1 = fmaxf(mx1, __shfl_xor_sync(0xffffffffu, mx1, 2));

            float mn0 = fmaxf(m_i[mi][0], mx0);
            float mn1 = fmaxf(m_i[mi][1], mx1);
            float corr0 = fexp2(m_i[mi][0] - mn0);
            float corr1 = fexp2(m_i[mi][1] - mn1);

            float rs0 = 0.0f, rs1 = 0.0f;
            #pragma unroll
            for (int nf = 0; nf < 8; ++nf) {
                s[mi][nf][0] = fexp2(s[mi][nf][0] - mn0);
                s[mi][nf][1] = fexp2(s[mi][nf][1] - mn0);
                s[mi][nf][2] = fexp2(s[mi][nf][2] - mn1);
                s[mi][nf][3] = fexp2(s[mi][nf][3] - mn1);
                rs0 += s[mi][nf][0] + s[mi][nf][1];
                rs1 += s[mi][nf][2] + s[mi][nf][3];
            }
            rs0 += __shfl_xor_sync(0xffffffffu, rs0, 1);
            rs0 += __shfl_xor_sync(0xffffffffu, rs0, 2);
            rs1 += __shfl_xor_sync(0xffffffffu, rs1, 1);
            rs1 += __shfl_xor_sync(0xffffffffu, rs1, 2);

            l_i[mi][0] = l_i[mi][0] * corr0 + rs0;
            l_i[mi][1] = l_i[mi][1] * corr1 + rs1;
            m_i[mi][0] = mn0;
            m_i[mi][1] = mn1;

            #pragma unroll
            for (int nf = 0; nf < 8; ++nf) {
                o[mi][nf][0] *= corr0; o[mi][nf][1] *= corr0;
                o[mi][nf][2] *= corr1; o[mi][nf][3] *= corr1;
            }

            #pragma unroll
            for (int kf = 0; kf < 4; ++kf) {
                pf[mi][kf][0] = packh(s[mi][2 * kf][0],     s[mi][2 * kf][1]);
                pf[mi][kf][1] = packh(s[mi][2 * kf][2],     s[mi][2 * kf][3]);
                pf[mi][kf][2] = packh(s[mi][2 * kf + 1][0], s[mi][2 * kf + 1][1]);
                pf[mi][kf][3] = packh(s[mi][2 * kf + 1][2], s[mi][2 * kf + 1][3]);
            }
        }

        // O += P @ V  (row-major V tile, B-frags via ldmatrix.trans)
        const uint32_t svw = svb + sb;
        #pragma unroll
        for (int kf = 0; kf < 4; ++kf) {
            #pragma unroll
            for (int nfp = 0; nfp < 4; ++nfp) {
                uint32_t bb[4];
                ldsm4t(bb, svw + (uint32_t)(kf * 16 * 36) * 4 + nfp * 32);
                #pragma unroll
                for (int mi = 0; mi < 2; ++mi) {
                    mma_f16(o[mi][2 * nfp],     pf[mi][kf], &bb[0]);
                    mma_f16(o[mi][2 * nfp + 1], pf[mi][kf], &bb[2]);
                }
            }
        }
    }

    // Normalize + store fp16 into [B, S, E]
    int bz = bh >> 3, h = bh & 7;
    #pragma unroll
    for (int mi = 0; mi < 2; ++mi) {
        float inv0 = 1.0f / l_i[mi][0];
        float inv1 = 1.0f / l_i[mi][1];
        int row0 = qt * 128 + w * 32 + mi * 16 + r;
        __half* op0 = O + ((size_t)bz * SEQ + row0) * EMBED + h * HDIM;
        __half* op1 = O + ((size_t)bz * SEQ + row0 + 8) * EMBED + h * HDIM;
        #pragma unroll
        for (int nf = 0; nf < 8; ++nf) {
            *(uint32_t*)(op0 + nf * 8 + 2 * cc) = packh(o[mi][nf][0] * inv0, o[mi][nf][1] * inv0);
            *(uint32_t*)(op1 + nf * 8 + 2 * cc) = packh(o[mi][nf][2] * inv1, o[mi][nf][3] * inv1);
        }
    }
}

extern "C" void kernel_launch(void* const* d_in, const int* in_sizes, int n_in,
                              void* d_out, int out_size) {
    const float* x  = (const float*)d_in[0];
    const float* Wq = (const float*)d_in[1];
    const float* bq = (const float*)d_in[2];
    const float* Wk = (const float*)d_in[3];
    const float* bk = (const float*)d_in[4];
    const float* Wv = (const float*)d_in[5];
    const float* bv = (const float*)d_in[6];
    const float* Wo = (const float*)d_in[7];
    const float* bo = (const float*)d_in[8];
    float* out = (float*)d_out;

    __half *gq, *gk, *gv, *go;
    cudaGetSymbolAddress((void**)&gq, g_q);
    cudaGetSymbolAddress((void**)&gk, g_k);
    cudaGetSymbolAddress((void**)&gv, g_v);
    cudaGetSymbolAddress((void**)&go, g_o);

    const int GEMM_SMEM  = 2 * 2 * 128 * 36 * 4;   // 73728
    const int FLASH_SMEM = 3 * 2 * 64 * 36 * 4;    // 55296
    cudaFuncSetAttribute(qkv_proj,  cudaFuncAttributeMaxDynamicSharedMemorySize, GEMM_SMEM);
    cudaFuncSetAttribute(out_proj,  cudaFuncAttributeMaxDynamicSharedMemorySize, GEMM_SMEM);
    cudaFuncSetAttribute(flash_mma, cudaFuncAttributeMaxDynamicSharedMemorySize, FLASH_SMEM);

    const int XC = MTOT * EMBED / 4;
    const int WC = EMBED * EMBED / 4;
    convert_f2h<<<(XC + 4 * WC) / 256, 256>>>(x, Wq, Wk, Wv, Wo);

    dim3 gridP(EMBED / 128, MTOT / 128, 3);   // (4, 64, 3)
    qkv_proj<<<gridP, 256, GEMM_SMEM>>>(bq, bk, bv);

    dim3 gridA(SEQ / 128, BATCH * NHEADS);    // (16, 32)
    flash_mma<<<gridA, 128, FLASH_SMEM>>>(gq, gk, gv, go);

    dim3 gridO(EMBED / 128, MTOT / 128);      // (4, 64)
    out_proj<<<gridO, 256, GEMM_SMEM>>>(bo, out);
}